// round 2
// baseline (speedup 1.0000x reference)
#include <cuda_runtime.h>
#include <math.h>

#define N       12288
#define D_K     8
#define H1      32
#define H2      16
#define N_EDGES 6144
#define N_TRI   4096
#define CAP     64

// ---------------- device scratch (no allocations allowed) ----------------
__device__ float    g_q[N * D_K];
__device__ float    g_k[N * D_K];
__device__ float    g_v[N * D_K];
__device__ float    g_logits[N];
__device__ float    g_e[N];
__device__ int      g_cnt[N_TRI];
__device__ int      g_mem[N_TRI * CAP];
__device__ unsigned g_segmax[N_EDGES];
__device__ float    g_segsum[N_EDGES];

// monotone float <-> uint encoding for atomicMax on floats
__device__ __forceinline__ unsigned f2o(float f) {
    unsigned u = __float_as_uint(f);
    return (u & 0x80000000u) ? ~u : (u | 0x80000000u);
}
__device__ __forceinline__ float o2f(unsigned e) {
    return (e & 0x80000000u) ? __uint_as_float(e ^ 0x80000000u)
                             : __uint_as_float(~e);
}

__device__ __forceinline__ float gelu_exact(float x) {
    return 0.5f * x * (1.0f + erff(x * 0.70710678118654752f));
}

// ---------------- K0: zero per-replay state ----------------
__global__ void k_zero() {
    int i = blockIdx.x * blockDim.x + threadIdx.x;
    if (i < N_TRI)   g_cnt[i] = 0;
    if (i < N_EDGES) { g_segmax[i] = 0u; g_segsum[i] = 0.0f; }
}

// ---------------- K1: q,k,v projections + triangle bucketing ----------------
__global__ void k_qkv(const float* __restrict__ ef, const int* __restrict__ tri,
                      const float* __restrict__ Wq, const float* __restrict__ bq,
                      const float* __restrict__ Wk, const float* __restrict__ bk,
                      const float* __restrict__ Wv, const float* __restrict__ bv) {
    int i = blockIdx.x * blockDim.x + threadIdx.x;
    if (i >= N) return;
    float x0 = ef[2 * i + 0];
    float x1 = ef[2 * i + 1];
#pragma unroll
    for (int o = 0; o < D_K; o++) {
        g_q[i * D_K + o] = fmaf(x0, Wq[o * 2], fmaf(x1, Wq[o * 2 + 1], bq[o]));
        g_k[i * D_K + o] = fmaf(x0, Wk[o * 2], fmaf(x1, Wk[o * 2 + 1], bk[o]));
        g_v[i * D_K + o] = fmaf(x0, Wv[o * 2], fmaf(x1, Wv[o * 2 + 1], bv[o]));
    }
    int t = tri[i];
    int p = atomicAdd(&g_cnt[t], 1);
    if (p < CAP) g_mem[t * CAP + p] = i;
}

// ---------------- K2: grouped attention + MLP + logits + segment max ----------------
__global__ __launch_bounds__(128)
void k_main(const int* __restrict__ tri, const int* __restrict__ eids,
            const float* __restrict__ W1, const float* __restrict__ b1,
            const float* __restrict__ ln1g, const float* __restrict__ ln1b,
            const float* __restrict__ rmsw,
            const float* __restrict__ Wr, const float* __restrict__ br,
            const float* __restrict__ ln2g, const float* __restrict__ ln2b,
            const float* __restrict__ W2, const float* __restrict__ b2,
            const float* __restrict__ W3, const float* __restrict__ b3) {
    __shared__ float sW1[H1 * D_K], sWr[H1 * H1], sW2[H2 * H1];
    __shared__ float sb1[H1], sg1[H1], sB1[H1], srw[H1], sbr[H1], sg2[H1], sB2[H1];
    __shared__ float sb2[H2], sW3[H2];
    __shared__ float sb3;

    int tid = threadIdx.x;
    for (int j = tid; j < H1 * D_K; j += blockDim.x) sW1[j] = W1[j];
    for (int j = tid; j < H1 * H1;  j += blockDim.x) sWr[j] = Wr[j];
    for (int j = tid; j < H2 * H1;  j += blockDim.x) sW2[j] = W2[j];
    if (tid < H1) {
        sb1[tid] = b1[tid];  sg1[tid] = ln1g[tid]; sB1[tid] = ln1b[tid];
        srw[tid] = rmsw[tid]; sbr[tid] = br[tid];
        sg2[tid] = ln2g[tid]; sB2[tid] = ln2b[tid];
    }
    if (tid < H2) { sb2[tid] = b2[tid]; sW3[tid] = W3[tid]; }
    if (tid == 0) sb3 = b3[0];
    __syncthreads();

    int i = blockIdx.x * blockDim.x + tid;
    if (i >= N) return;

    // ---- grouped attention ----
    float q[D_K];
#pragma unroll
    for (int o = 0; o < D_K; o++) q[o] = g_q[i * D_K + o];

    int t = tri[i];
    int c = min(g_cnt[t], CAP);
    const float isq = 0.35355339059327373f;  // 1/sqrt(8)

    float m = -1e30f;
    for (int jj = 0; jj < c; jj++) {
        int j = g_mem[t * CAP + jj];
        float s = 0.0f;
#pragma unroll
        for (int o = 0; o < D_K; o++) s = fmaf(q[o], g_k[j * D_K + o], s);
        m = fmaxf(m, s * isq);
    }
    float se = 0.0f, acc[D_K];
#pragma unroll
    for (int o = 0; o < D_K; o++) acc[o] = 0.0f;
    for (int jj = 0; jj < c; jj++) {
        int j = g_mem[t * CAP + jj];
        float s = 0.0f;
#pragma unroll
        for (int o = 0; o < D_K; o++) s = fmaf(q[o], g_k[j * D_K + o], s);
        float e = expf(s * isq - m);
        se += e;
#pragma unroll
        for (int o = 0; o < D_K; o++) acc[o] = fmaf(e, g_v[j * D_K + o], acc[o]);
    }
    float inv_se = 1.0f / se;
    float att[D_K];
#pragma unroll
    for (int o = 0; o < D_K; o++) att[o] = acc[o] * inv_se;

    // ---- MLP ----
    float h[H1];
#pragma unroll
    for (int o = 0; o < H1; o++) {
        float s = sb1[o];
#pragma unroll
        for (int kk = 0; kk < D_K; kk++) s = fmaf(att[kk], sW1[o * D_K + kk], s);
        h[o] = s;
    }
    // layernorm 1 + gelu
    {
        float mu = 0.0f;
#pragma unroll
        for (int o = 0; o < H1; o++) mu += h[o];
        mu *= (1.0f / H1);
        float var = 0.0f;
#pragma unroll
        for (int o = 0; o < H1; o++) { float d = h[o] - mu; var = fmaf(d, d, var); }
        var *= (1.0f / H1);
        float inv = rsqrtf(var + 1e-5f);
#pragma unroll
        for (int o = 0; o < H1; o++)
            h[o] = gelu_exact((h[o] - mu) * inv * sg1[o] + sB1[o]);
    }
    // rmsnorm -> linear -> relu -> residual
    {
        float ss = 0.0f;
#pragma unroll
        for (int o = 0; o < H1; o++) ss = fmaf(h[o], h[o], ss);
        float rms = sqrtf(ss * (1.0f / H1));
        float inv = 1.0f / (rms + 1e-6f);
        float xn[H1];
#pragma unroll
        for (int o = 0; o < H1; o++) xn[o] = h[o] * inv * srw[o];
#pragma unroll
        for (int o = 0; o < H1; o++) {
            float s = sbr[o];
#pragma unroll
            for (int kk = 0; kk < H1; kk++) s = fmaf(xn[kk], sWr[o * H1 + kk], s);
            h[o] += fmaxf(s, 0.0f);
        }
    }
    // layernorm 2
    {
        float mu = 0.0f;
#pragma unroll
        for (int o = 0; o < H1; o++) mu += h[o];
        mu *= (1.0f / H1);
        float var = 0.0f;
#pragma unroll
        for (int o = 0; o < H1; o++) { float d = h[o] - mu; var = fmaf(d, d, var); }
        var *= (1.0f / H1);
        float inv = rsqrtf(var + 1e-5f);
#pragma unroll
        for (int o = 0; o < H1; o++)
            h[o] = (h[o] - mu) * inv * sg2[o] + sB2[o];
    }
    // linear 32->16 + gelu, linear 16->1
    float lg = sb3;
#pragma unroll
    for (int o = 0; o < H2; o++) {
        float s = sb2[o];
#pragma unroll
        for (int kk = 0; kk < H1; kk++) s = fmaf(h[kk], sW2[o * H1 + kk], s);
        lg = fmaf(gelu_exact(s), sW3[o], lg);
    }
    g_logits[i] = lg;
    atomicMax(&g_segmax[eids[i]], f2o(lg));
}

// ---------------- K3: exp + segment sum ----------------
__global__ void k_exp(const int* __restrict__ eids) {
    int i = blockIdx.x * blockDim.x + threadIdx.x;
    if (i >= N) return;
    int s = eids[i];
    float mx = o2f(g_segmax[s]);
    float e = expf(g_logits[i] - mx);
    g_e[i] = e;
    atomicAdd(&g_segsum[s], e);
}

// ---------------- K4: normalize ----------------
__global__ void k_out(const int* __restrict__ eids, float* __restrict__ out) {
    int i = blockIdx.x * blockDim.x + threadIdx.x;
    if (i >= N) return;
    out[i] = g_e[i] / g_segsum[eids[i]];
}

extern "C" void kernel_launch(void* const* d_in, const int* in_sizes, int n_in,
                              void* d_out, int out_size) {
    const float* ef   = (const float*)d_in[0];
    const int*   eids = (const int*)  d_in[1];
    const int*   tri  = (const int*)  d_in[2];
    const float* Wq = (const float*)d_in[3];  const float* bq = (const float*)d_in[4];
    const float* Wk = (const float*)d_in[5];  const float* bk = (const float*)d_in[6];
    const float* Wv = (const float*)d_in[7];  const float* bv = (const float*)d_in[8];
    const float* W1 = (const float*)d_in[9];  const float* b1 = (const float*)d_in[10];
    const float* g1 = (const float*)d_in[11]; const float* B1 = (const float*)d_in[12];
    const float* rw = (const float*)d_in[13];
    const float* Wr = (const float*)d_in[14]; const float* br = (const float*)d_in[15];
    const float* g2 = (const float*)d_in[16]; const float* B2 = (const float*)d_in[17];
    const float* W2 = (const float*)d_in[18]; const float* b2 = (const float*)d_in[19];
    const float* W3 = (const float*)d_in[20]; const float* b3 = (const float*)d_in[21];
    float* out = (float*)d_out;

    k_zero<<<(N_EDGES + 255) / 256, 256>>>();
    k_qkv <<<(N + 255) / 256, 256>>>(ef, tri, Wq, bq, Wk, bk, Wv, bv);
    k_main<<<(N + 127) / 128, 128>>>(tri, eids, W1, b1, g1, B1, rw, Wr, br,
                                     g2, B2, W2, b2, W3, b3);
    k_exp <<<(N + 255) / 256, 256>>>(eids);
    k_out <<<(N + 255) / 256, 256>>>(eids, out);
}

// round 3
// speedup vs baseline: 1.0738x; 1.0738x over previous
#include <cuda_runtime.h>
#include <math.h>

#define N       12288
#define D_K     8
#define H1      32
#define H2      16
#define N_EDGES 6144
#define N_TRI   4096
#define CAP     64

// ---------------- device scratch (no allocations allowed) ----------------
__device__ float    g_q[N * D_K];
__device__ float    g_k[N * D_K];
__device__ float    g_v[N * D_K];
__device__ float    g_logits[N];
__device__ float    g_e[N];
__device__ int      g_cnt[N_TRI];
__device__ int      g_mem[N_TRI * CAP];
__device__ unsigned g_segmax[N_EDGES];
__device__ float    g_segsum[N_EDGES];

// monotone float <-> uint encoding for atomicMax on floats
__device__ __forceinline__ unsigned f2o(float f) {
    unsigned u = __float_as_uint(f);
    return (u & 0x80000000u) ? ~u : (u | 0x80000000u);
}
__device__ __forceinline__ float o2f(unsigned e) {
    return (e & 0x80000000u) ? __uint_as_float(e ^ 0x80000000u)
                             : __uint_as_float(~e);
}

__device__ __forceinline__ float gelu_exact(float x) {
    return 0.5f * x * (1.0f + erff(x * 0.70710678118654752f));
}

// ---------------- K0: zero per-replay state ----------------
__global__ void k_zero() {
    int i = blockIdx.x * blockDim.x + threadIdx.x;
    if (i < N_TRI)   g_cnt[i] = 0;
    if (i < N_EDGES) { g_segmax[i] = 0u; g_segsum[i] = 0.0f; }
}

// ---------------- K1: q,k,v projections + triangle bucketing ----------------
__global__ void k_qkv(const float* __restrict__ ef, const int* __restrict__ tri,
                      const float* __restrict__ Wq, const float* __restrict__ bq,
                      const float* __restrict__ Wk, const float* __restrict__ bk,
                      const float* __restrict__ Wv, const float* __restrict__ bv) {
    int i = blockIdx.x * blockDim.x + threadIdx.x;
    if (i >= N) return;
    float x0 = ef[2 * i + 0];
    float x1 = ef[2 * i + 1];
#pragma unroll
    for (int o = 0; o < D_K; o++) {
        g_q[i * D_K + o] = fmaf(x0, Wq[o * 2], fmaf(x1, Wq[o * 2 + 1], bq[o]));
        g_k[i * D_K + o] = fmaf(x0, Wk[o * 2], fmaf(x1, Wk[o * 2 + 1], bk[o]));
        g_v[i * D_K + o] = fmaf(x0, Wv[o * 2], fmaf(x1, Wv[o * 2 + 1], bv[o]));
    }
    int t = tri[i];
    int p = atomicAdd(&g_cnt[t], 1);
    if (p < CAP) g_mem[t * CAP + p] = i;
}

// ---------------- K2: grouped attention + MLP + logits + segment max ----------------
__global__ __launch_bounds__(128)
void k_main(const int* __restrict__ tri, const int* __restrict__ eids,
            const float* __restrict__ W1, const float* __restrict__ b1,
            const float* __restrict__ ln1g, const float* __restrict__ ln1b,
            const float* __restrict__ rmsw,
            const float* __restrict__ Wr, const float* __restrict__ br,
            const float* __restrict__ ln2g, const float* __restrict__ ln2b,
            const float* __restrict__ W2, const float* __restrict__ b2,
            const float* __restrict__ W3, const float* __restrict__ b3) {
    __shared__ float sW1[H1 * D_K], sWr[H1 * H1], sW2[H2 * H1];
    __shared__ float sb1[H1], sg1[H1], sB1[H1], srw[H1], sbr[H1], sg2[H1], sB2[H1];
    __shared__ float sb2[H2], sW3[H2];
    __shared__ float sb3;

    int tid = threadIdx.x;
    for (int j = tid; j < H1 * D_K; j += blockDim.x) sW1[j] = W1[j];
    for (int j = tid; j < H1 * H1;  j += blockDim.x) sWr[j] = Wr[j];
    for (int j = tid; j < H2 * H1;  j += blockDim.x) sW2[j] = W2[j];
    if (tid < H1) {
        sb1[tid] = b1[tid];  sg1[tid] = ln1g[tid]; sB1[tid] = ln1b[tid];
        srw[tid] = rmsw[tid]; sbr[tid] = br[tid];
        sg2[tid] = ln2g[tid]; sB2[tid] = ln2b[tid];
    }
    if (tid < H2) { sb2[tid] = b2[tid]; sW3[tid] = W3[tid]; }
    if (tid == 0) sb3 = b3[0];
    __syncthreads();

    int i = blockIdx.x * blockDim.x + tid;
    if (i >= N) return;

    // ---- grouped attention ----
    float q[D_K];
#pragma unroll
    for (int o = 0; o < D_K; o++) q[o] = g_q[i * D_K + o];

    int t = tri[i];
    int c = min(g_cnt[t], CAP);
    const float isq = 0.35355339059327373f;  // 1/sqrt(8)

    float m = -1e30f;
    for (int jj = 0; jj < c; jj++) {
        int j = g_mem[t * CAP + jj];
        float s = 0.0f;
#pragma unroll
        for (int o = 0; o < D_K; o++) s = fmaf(q[o], g_k[j * D_K + o], s);
        m = fmaxf(m, s * isq);
    }
    float se = 0.0f, acc[D_K];
#pragma unroll
    for (int o = 0; o < D_K; o++) acc[o] = 0.0f;
    for (int jj = 0; jj < c; jj++) {
        int j = g_mem[t * CAP + jj];
        float s = 0.0f;
#pragma unroll
        for (int o = 0; o < D_K; o++) s = fmaf(q[o], g_k[j * D_K + o], s);
        float e = expf(s * isq - m);
        se += e;
#pragma unroll
        for (int o = 0; o < D_K; o++) acc[o] = fmaf(e, g_v[j * D_K + o], acc[o]);
    }
    float inv_se = 1.0f / se;
    float att[D_K];
#pragma unroll
    for (int o = 0; o < D_K; o++) att[o] = acc[o] * inv_se;

    // ---- MLP ----
    float h[H1];
#pragma unroll
    for (int o = 0; o < H1; o++) {
        float s = sb1[o];
#pragma unroll
        for (int kk = 0; kk < D_K; kk++) s = fmaf(att[kk], sW1[o * D_K + kk], s);
        h[o] = s;
    }
    // layernorm 1 + gelu
    {
        float mu = 0.0f;
#pragma unroll
        for (int o = 0; o < H1; o++) mu += h[o];
        mu *= (1.0f / H1);
        float var = 0.0f;
#pragma unroll
        for (int o = 0; o < H1; o++) { float d = h[o] - mu; var = fmaf(d, d, var); }
        var *= (1.0f / H1);
        float inv = rsqrtf(var + 1e-5f);
#pragma unroll
        for (int o = 0; o < H1; o++)
            h[o] = gelu_exact((h[o] - mu) * inv * sg1[o] + sB1[o]);
    }
    // rmsnorm -> linear -> relu -> residual
    {
        float ss = 0.0f;
#pragma unroll
        for (int o = 0; o < H1; o++) ss = fmaf(h[o], h[o], ss);
        float rms = sqrtf(ss * (1.0f / H1));
        float inv = 1.0f / (rms + 1e-6f);
        float xn[H1];
#pragma unroll
        for (int o = 0; o < H1; o++) xn[o] = h[o] * inv * srw[o];
#pragma unroll
        for (int o = 0; o < H1; o++) {
            float s = sbr[o];
#pragma unroll
            for (int kk = 0; kk < H1; kk++) s = fmaf(xn[kk], sWr[o * H1 + kk], s);
            h[o] += fmaxf(s, 0.0f);
        }
    }
    // layernorm 2
    {
        float mu = 0.0f;
#pragma unroll
        for (int o = 0; o < H1; o++) mu += h[o];
        mu *= (1.0f / H1);
        float var = 0.0f;
#pragma unroll
        for (int o = 0; o < H1; o++) { float d = h[o] - mu; var = fmaf(d, d, var); }
        var *= (1.0f / H1);
        float inv = rsqrtf(var + 1e-5f);
#pragma unroll
        for (int o = 0; o < H1; o++)
            h[o] = (h[o] - mu) * inv * sg2[o] + sB2[o];
    }
    // linear 32->16 + gelu, linear 16->1
    float lg = sb3;
#pragma unroll
    for (int o = 0; o < H2; o++) {
        float s = sb2[o];
#pragma unroll
        for (int kk = 0; kk < H1; kk++) s = fmaf(h[kk], sW2[o * H1 + kk], s);
        lg = fmaf(gelu_exact(s), sW3[o], lg);
    }
    g_logits[i] = lg;
    atomicMax(&g_segmax[eids[i]], f2o(lg));
}

// ---------------- K3: exp + segment sum ----------------
__global__ void k_exp(const int* __restrict__ eids) {
    int i = blockIdx.x * blockDim.x + threadIdx.x;
    if (i >= N) return;
    int s = eids[i];
    float mx = o2f(g_segmax[s]);
    float e = expf(g_logits[i] - mx);
    g_e[i] = e;
    atomicAdd(&g_segsum[s], e);
}

// ---------------- K4: normalize ----------------
__global__ void k_out(const int* __restrict__ eids, float* __restrict__ out) {
    int i = blockIdx.x * blockDim.x + threadIdx.x;
    if (i >= N) return;
    out[i] = g_e[i] / g_segsum[eids[i]];
}

extern "C" void kernel_launch(void* const* d_in, const int* in_sizes, int n_in,
                              void* d_out, int out_size) {
    const float* ef   = (const float*)d_in[0];
    const int*   eids = (const int*)  d_in[1];
    const int*   tri  = (const int*)  d_in[2];
    const float* Wq = (const float*)d_in[3];  const float* bq = (const float*)d_in[4];
    const float* Wk = (const float*)d_in[5];  const float* bk = (const float*)d_in[6];
    const float* Wv = (const float*)d_in[7];  const float* bv = (const float*)d_in[8];
    const float* W1 = (const float*)d_in[9];  const float* b1 = (const float*)d_in[10];
    const float* g1 = (const float*)d_in[11]; const float* B1 = (const float*)d_in[12];
    const float* rw = (const float*)d_in[13];
    const float* Wr = (const float*)d_in[14]; const float* br = (const float*)d_in[15];
    const float* g2 = (const float*)d_in[16]; const float* B2 = (const float*)d_in[17];
    const float* W2 = (const float*)d_in[18]; const float* b2 = (const float*)d_in[19];
    const float* W3 = (const float*)d_in[20]; const float* b3 = (const float*)d_in[21];
    float* out = (float*)d_out;

    k_zero<<<(N_EDGES + 255) / 256, 256>>>();
    k_qkv <<<(N + 255) / 256, 256>>>(ef, tri, Wq, bq, Wk, bk, Wv, bv);
    k_main<<<(N + 127) / 128, 128>>>(tri, eids, W1, b1, g1, B1, rw, Wr, br,
                                     g2, B2, W2, b2, W3, b3);
    k_exp <<<(N + 255) / 256, 256>>>(eids);
    k_out <<<(N + 255) / 256, 256>>>(eids, out);
}

// round 4
// speedup vs baseline: 1.1963x; 1.1142x over previous
#include <cuda_runtime.h>
#include <math.h>

#define N       12288
#define D_K     8
#define H1      32
#define H2      16
#define N_EDGES 6144
#define N_TRI   4096
#define CAP     64
#define ECAP    32
#define NB      96
#define TPB     128

// ---------------- device scratch (zero-initialized at module load) ----------------
__device__ float    g_q[N * D_K];
__device__ float    g_k[N * D_K];
__device__ float    g_v[N * D_K];
__device__ float    g_logits[N];
__device__ int      g_cnt[N_TRI];           // zeroed at end of each call
__device__ int      g_mem[N_TRI * CAP];
__device__ int      g_ecnt[N_EDGES];        // zeroed at end of each call
__device__ int      g_emem[N_EDGES * ECAP];
__device__ unsigned g_bar1, g_bar2, g_bar3; // reset at end of each call

__device__ __forceinline__ float gelu_exact(float x) {
    return 0.5f * x * (1.0f + erff(x * 0.70710678118654752f));
}

// software grid barrier — safe because grid (96 blocks) is strictly one wave
__device__ __forceinline__ void grid_barrier(unsigned* ctr) {
    __syncthreads();
    if (threadIdx.x == 0) {
        __threadfence();                       // release phase-1 writes to L2
        atomicAdd(ctr, 1u);
        while (*(volatile unsigned*)ctr < NB) {}
        __threadfence();                       // acquire
    }
    __syncthreads();
}

__global__ __launch_bounds__(TPB, 1)
void k_fused(const float* __restrict__ ef, const int* __restrict__ eids,
             const int* __restrict__ tri,
             const float* __restrict__ Wq, const float* __restrict__ bq,
             const float* __restrict__ Wk, const float* __restrict__ bk,
             const float* __restrict__ Wv, const float* __restrict__ bv,
             const float* __restrict__ W1, const float* __restrict__ b1,
             const float* __restrict__ ln1g, const float* __restrict__ ln1b,
             const float* __restrict__ rmsw,
             const float* __restrict__ Wr, const float* __restrict__ br,
             const float* __restrict__ ln2g, const float* __restrict__ ln2b,
             const float* __restrict__ W2, const float* __restrict__ b2,
             const float* __restrict__ W3, const float* __restrict__ b3,
             float* __restrict__ out) {
    __shared__ float sW1[H1 * D_K], sWr[H1 * H1], sW2[H2 * H1];
    __shared__ float sb1[H1], sg1[H1], sB1[H1], srw[H1], sbr[H1], sg2[H1], sB2[H1];
    __shared__ float sb2[H2], sW3[H2];
    __shared__ float sb3;

    const int tid = threadIdx.x;
    const int i   = blockIdx.x * TPB + tid;   // 0..N-1, exact cover

    // ---- stage MLP weights into shared (overlaps with phase 1) ----
    for (int j = tid; j < H1 * D_K; j += TPB) sW1[j] = W1[j];
    for (int j = tid; j < H1 * H1;  j += TPB) sWr[j] = Wr[j];
    for (int j = tid; j < H2 * H1;  j += TPB) sW2[j] = W2[j];
    if (tid < H1) {
        sb1[tid] = b1[tid];   sg1[tid] = ln1g[tid]; sB1[tid] = ln1b[tid];
        srw[tid] = rmsw[tid]; sbr[tid] = br[tid];
        sg2[tid] = ln2g[tid]; sB2[tid] = ln2b[tid];
    }
    if (tid < H2) { sb2[tid] = b2[tid]; sW3[tid] = W3[tid]; }
    if (tid == 0) sb3 = b3[0];

    // ================= Phase 1: qkv + bucketing =================
    {
        float x0 = ef[2 * i + 0];
        float x1 = ef[2 * i + 1];
#pragma unroll
        for (int o = 0; o < D_K; o++) {
            g_q[i * D_K + o] = fmaf(x0, Wq[o * 2], fmaf(x1, Wq[o * 2 + 1], bq[o]));
            g_k[i * D_K + o] = fmaf(x0, Wk[o * 2], fmaf(x1, Wk[o * 2 + 1], bk[o]));
            g_v[i * D_K + o] = fmaf(x0, Wv[o * 2], fmaf(x1, Wv[o * 2 + 1], bv[o]));
        }
        int t = tri[i];
        int p = atomicAdd(&g_cnt[t], 1);
        if (p < CAP) g_mem[t * CAP + p] = i;
        int e  = eids[i];
        int pe = atomicAdd(&g_ecnt[e], 1);
        if (pe < ECAP) g_emem[e * ECAP + pe] = i;
    }

    grid_barrier(&g_bar1);

    // ================= Phase 2: attention + MLP -> logits =================
    {
        float q[D_K];
#pragma unroll
        for (int o = 0; o < D_K; o++) q[o] = g_q[i * D_K + o];

        int t = tri[i];
        int c = min(g_cnt[t], CAP);
        const float isq = 0.35355339059327373f;  // 1/sqrt(8)
        const float4* k4 = (const float4*)g_k;
        const float4* v4 = (const float4*)g_v;

        float m = -1e30f;
        for (int jj = 0; jj < c; jj++) {
            int j = g_mem[t * CAP + jj];
            float4 ka = k4[j * 2], kb = k4[j * 2 + 1];
            float s = q[0]*ka.x + q[1]*ka.y + q[2]*ka.z + q[3]*ka.w
                    + q[4]*kb.x + q[5]*kb.y + q[6]*kb.z + q[7]*kb.w;
            m = fmaxf(m, s * isq);
        }
        float se = 0.0f, acc[D_K];
#pragma unroll
        for (int o = 0; o < D_K; o++) acc[o] = 0.0f;
        for (int jj = 0; jj < c; jj++) {
            int j = g_mem[t * CAP + jj];
            float4 ka = k4[j * 2], kb = k4[j * 2 + 1];
            float s = q[0]*ka.x + q[1]*ka.y + q[2]*ka.z + q[3]*ka.w
                    + q[4]*kb.x + q[5]*kb.y + q[6]*kb.z + q[7]*kb.w;
            float e = expf(s * isq - m);
            se += e;
            float4 va = v4[j * 2], vb = v4[j * 2 + 1];
            acc[0] = fmaf(e, va.x, acc[0]); acc[1] = fmaf(e, va.y, acc[1]);
            acc[2] = fmaf(e, va.z, acc[2]); acc[3] = fmaf(e, va.w, acc[3]);
            acc[4] = fmaf(e, vb.x, acc[4]); acc[5] = fmaf(e, vb.y, acc[5]);
            acc[6] = fmaf(e, vb.z, acc[6]); acc[7] = fmaf(e, vb.w, acc[7]);
        }
        float inv_se = 1.0f / se;
        float att[D_K];
#pragma unroll
        for (int o = 0; o < D_K; o++) att[o] = acc[o] * inv_se;

        // ---- MLP ----
        float h[H1];
#pragma unroll
        for (int o = 0; o < H1; o++) {
            float s = sb1[o];
#pragma unroll
            for (int kk = 0; kk < D_K; kk++) s = fmaf(att[kk], sW1[o * D_K + kk], s);
            h[o] = s;
        }
        // layernorm 1 + gelu
        {
            float mu = 0.0f;
#pragma unroll
            for (int o = 0; o < H1; o++) mu += h[o];
            mu *= (1.0f / H1);
            float var = 0.0f;
#pragma unroll
            for (int o = 0; o < H1; o++) { float d = h[o] - mu; var = fmaf(d, d, var); }
            var *= (1.0f / H1);
            float inv = rsqrtf(var + 1e-5f);
#pragma unroll
            for (int o = 0; o < H1; o++)
                h[o] = gelu_exact((h[o] - mu) * inv * sg1[o] + sB1[o]);
        }
        // rmsnorm -> linear -> relu -> residual
        {
            float ss = 0.0f;
#pragma unroll
            for (int o = 0; o < H1; o++) ss = fmaf(h[o], h[o], ss);
            float rms = sqrtf(ss * (1.0f / H1));
            float inv = 1.0f / (rms + 1e-6f);
            float xn[H1];
#pragma unroll
            for (int o = 0; o < H1; o++) xn[o] = h[o] * inv * srw[o];
#pragma unroll
            for (int o = 0; o < H1; o++) {
                float s = sbr[o];
#pragma unroll
                for (int kk = 0; kk < H1; kk++) s = fmaf(xn[kk], sWr[o * H1 + kk], s);
                h[o] += fmaxf(s, 0.0f);
            }
        }
        // layernorm 2
        {
            float mu = 0.0f;
#pragma unroll
            for (int o = 0; o < H1; o++) mu += h[o];
            mu *= (1.0f / H1);
            float var = 0.0f;
#pragma unroll
            for (int o = 0; o < H1; o++) { float d = h[o] - mu; var = fmaf(d, d, var); }
            var *= (1.0f / H1);
            float inv = rsqrtf(var + 1e-5f);
#pragma unroll
            for (int o = 0; o < H1; o++)
                h[o] = (h[o] - mu) * inv * sg2[o] + sB2[o];
        }
        // linear 32->16 + gelu, linear 16->1
        float lg = sb3;
#pragma unroll
        for (int o = 0; o < H2; o++) {
            float s = sb2[o];
#pragma unroll
            for (int kk = 0; kk < H1; kk++) s = fmaf(h[kk], sW2[o * H1 + kk], s);
            lg = fmaf(gelu_exact(s), sW3[o], lg);
        }
        g_logits[i] = lg;
    }

    grid_barrier(&g_bar2);

    // ================= Phase 3: per-edge-segment softmax =================
    if (i < N_EDGES) {
        int c = min(g_ecnt[i], ECAP);
        g_ecnt[i] = 0;                         // reset for next replay
        if (c > 0) {
            float lv[ECAP];
            int   jv[ECAP];
            float mx = -1e30f;
            for (int jj = 0; jj < c; jj++) {
                int j = g_emem[i * ECAP + jj];
                float l = g_logits[j];
                jv[jj] = j; lv[jj] = l;
                mx = fmaxf(mx, l);
            }
            float sum = 0.0f;
            for (int jj = 0; jj < c; jj++) {
                float e = expf(lv[jj] - mx);
                lv[jj] = e;
                sum += e;
            }
            float inv = 1.0f / sum;
            for (int jj = 0; jj < c; jj++)
                out[jv[jj]] = lv[jj] * inv;
        }
    }
    if (i < N_TRI) g_cnt[i] = 0;               // reset for next replay

    // ---- final arrival: last block resets barrier counters ----
    __syncthreads();
    if (tid == 0) {
        __threadfence();
        unsigned prev = atomicAdd(&g_bar3, 1u);
        if (prev == NB - 1u) {
            g_bar1 = 0u; g_bar2 = 0u; g_bar3 = 0u;
            __threadfence();
        }
    }
}

extern "C" void kernel_launch(void* const* d_in, const int* in_sizes, int n_in,
                              void* d_out, int out_size) {
    const float* ef   = (const float*)d_in[0];
    const int*   eids = (const int*)  d_in[1];
    const int*   tri  = (const int*)  d_in[2];
    const float* Wq = (const float*)d_in[3];  const float* bq = (const float*)d_in[4];
    const float* Wk = (const float*)d_in[5];  const float* bk = (const float*)d_in[6];
    const float* Wv = (const float*)d_in[7];  const float* bv = (const float*)d_in[8];
    const float* W1 = (const float*)d_in[9];  const float* b1 = (const float*)d_in[10];
    const float* g1 = (const float*)d_in[11]; const float* B1 = (const float*)d_in[12];
    const float* rw = (const float*)d_in[13];
    const float* Wr = (const float*)d_in[14]; const float* br = (const float*)d_in[15];
    const float* g2 = (const float*)d_in[16]; const float* B2 = (const float*)d_in[17];
    const float* W2 = (const float*)d_in[18]; const float* b2 = (const float*)d_in[19];
    const float* W3 = (const float*)d_in[20]; const float* b3 = (const float*)d_in[21];
    float* out = (float*)d_out;

    k_fused<<<NB, TPB>>>(ef, eids, tri, Wq, bq, Wk, bk, Wv, bv,
                         W1, b1, g1, B1, rw, Wr, br, g2, B2, W2, b2, W3, b3, out);
}

// round 5
// speedup vs baseline: 1.3232x; 1.1061x over previous
#include <cuda_runtime.h>
#include <math.h>

#define N       12288
#define D_K     8
#define H1      32
#define H2      16
#define N_EDGES 6144
#define N_TRI   4096
#define CAP     64
#define ECAP    32
#define NB      96
#define TPB     512
#define RPB     128   // rows per block (TPB/4)

// ---------------- device scratch (zero-initialized at module load) ----------------
__device__ float    g_q[N * D_K];
__device__ float    g_k[N * D_K];
__device__ float    g_v[N * D_K];
__device__ float    g_logits[N];
__device__ int      g_cnt[N_TRI];           // zeroed at end of each call
__device__ int      g_mem[N_TRI * CAP];
__device__ int      g_ecnt[N_EDGES];        // zeroed at end of each call
__device__ int      g_emem[N_EDGES * ECAP];
__device__ unsigned g_bar1, g_bar2, g_bar3; // reset at end of each call

__device__ __forceinline__ float gelu_exact(float x) {
    return 0.5f * x * (1.0f + erff(x * 0.70710678118654752f));
}

// software grid barrier — safe: 96 blocks is strictly one wave on 148 SMs
__device__ __forceinline__ void grid_barrier(unsigned* ctr) {
    __syncthreads();
    if (threadIdx.x == 0) {
        __threadfence();
        atomicAdd(ctr, 1u);
        while (*(volatile unsigned*)ctr < NB) {}
        __threadfence();
    }
    __syncthreads();
}

__global__ __launch_bounds__(TPB, 1)
void k_fused(const float* __restrict__ ef, const int* __restrict__ eids,
             const int* __restrict__ tri,
             const float* __restrict__ Wq, const float* __restrict__ bq,
             const float* __restrict__ Wk, const float* __restrict__ bk,
             const float* __restrict__ Wv, const float* __restrict__ bv,
             const float* __restrict__ W1, const float* __restrict__ b1,
             const float* __restrict__ ln1g, const float* __restrict__ ln1b,
             const float* __restrict__ rmsw,
             const float* __restrict__ Wr, const float* __restrict__ br,
             const float* __restrict__ ln2g, const float* __restrict__ ln2b,
             const float* __restrict__ W2, const float* __restrict__ b2,
             const float* __restrict__ W3, const float* __restrict__ b3,
             float* __restrict__ out) {
    // padded shared weights (odd strides -> conflict-free for 4-lane groups)
    __shared__ float sW1[H1 * 9];        // [o*9 + k], k<8
    __shared__ float sWr[H1 * 33];       // [o*33 + k], k<32
    __shared__ float sW2[H2 * 33];       // [o*33 + k], k<32
    __shared__ float sb1[H1], sg1[H1], sB1[H1], srw[H1], sbr[H1], sg2[H1], sB2[H1];
    __shared__ float sb2[H2], sW3[H2];
    __shared__ float sb3;
    __shared__ float sh[RPB * 33];       // per-row 32-vector scratch, padded

    const int tid = threadIdx.x;
    const int sub = tid & 3;             // lane within 4-lane row group
    const int rl  = tid >> 2;            // local row
    const int i   = blockIdx.x * RPB + rl;
    const int lane = tid & 31;
    const unsigned gmask = 0xFu << (lane & ~3);   // this group's shuffle mask

    // ---- stage weights (overlaps phase 1) ----
    for (int j = tid; j < H1 * D_K; j += TPB) sW1[(j >> 3) * 9  + (j & 7)]  = W1[j];
    for (int j = tid; j < H1 * H1;  j += TPB) sWr[(j >> 5) * 33 + (j & 31)] = Wr[j];
    for (int j = tid; j < H2 * H1;  j += TPB) sW2[(j >> 5) * 33 + (j & 31)] = W2[j];
    if (tid < H1) {
        sb1[tid] = b1[tid];   sg1[tid] = ln1g[tid]; sB1[tid] = ln1b[tid];
        srw[tid] = rmsw[tid]; sbr[tid] = br[tid];
        sg2[tid] = ln2g[tid]; sB2[tid] = ln2b[tid];
    }
    if (tid < H2) { sb2[tid] = b2[tid]; sW3[tid] = W3[tid]; }
    if (tid == 0) sb3 = b3[0];

    // ================= Phase 1: qkv (2 dims/lane) + bucketing =================
    {
        float x0 = ef[2 * i + 0];
        float x1 = ef[2 * i + 1];
        int o0 = 2 * sub;
        float2 qv, kv, vv;
        qv.x = fmaf(x0, Wq[o0*2],     fmaf(x1, Wq[o0*2+1],     bq[o0]));
        qv.y = fmaf(x0, Wq[(o0+1)*2], fmaf(x1, Wq[(o0+1)*2+1], bq[o0+1]));
        kv.x = fmaf(x0, Wk[o0*2],     fmaf(x1, Wk[o0*2+1],     bk[o0]));
        kv.y = fmaf(x0, Wk[(o0+1)*2], fmaf(x1, Wk[(o0+1)*2+1], bk[o0+1]));
        vv.x = fmaf(x0, Wv[o0*2],     fmaf(x1, Wv[o0*2+1],     bv[o0]));
        vv.y = fmaf(x0, Wv[(o0+1)*2], fmaf(x1, Wv[(o0+1)*2+1], bv[o0+1]));
        ((float2*)g_q)[i * 4 + sub] = qv;
        ((float2*)g_k)[i * 4 + sub] = kv;
        ((float2*)g_v)[i * 4 + sub] = vv;
        if (sub == 0) {
            int t = tri[i];
            int p = atomicAdd(&g_cnt[t], 1);
            if (p < CAP) g_mem[t * CAP + p] = i;
            int e  = eids[i];
            int pe = atomicAdd(&g_ecnt[e], 1);
            if (pe < ECAP) g_emem[e * ECAP + pe] = i;
        }
    }

    grid_barrier(&g_bar1);

    // ================= Phase 2: attention + MLP -> logits =================
    {
        float2 q2 = ((const float2*)g_q)[i * 4 + sub];
        int t = tri[i];
        int c = min(g_cnt[t], CAP);
        const float isq = 0.35355339059327373f;  // 1/sqrt(8)

        // single-pass softmax (scores bounded; normalization identical)
        float se = 0.0f, a0 = 0.0f, a1 = 0.0f;
        for (int jj = 0; jj < c; jj++) {
            int j = g_mem[t * CAP + jj];
            float2 k2 = ((const float2*)g_k)[j * 4 + sub];
            float p = q2.x * k2.x + q2.y * k2.y;
            p += __shfl_xor_sync(gmask, p, 1);
            p += __shfl_xor_sync(gmask, p, 2);
            float e = expf(p * isq);
            se += e;
            float2 v2 = ((const float2*)g_v)[j * 4 + sub];
            a0 = fmaf(e, v2.x, a0);
            a1 = fmaf(e, v2.y, a1);
        }
        float inv_se = 1.0f / se;
        float att0 = a0 * inv_se, att1 = a1 * inv_se;

        // broadcast full att[8] to all 4 lanes of the group
        float att[D_K];
#pragma unroll
        for (int s2 = 0; s2 < 4; s2++) {
            att[2*s2]   = __shfl_sync(gmask, att0, s2, 4);
            att[2*s2+1] = __shfl_sync(gmask, att1, s2, 4);
        }

        // ---- MLP: this lane owns outputs o = 8*sub .. 8*sub+7 ----
        const int ob = 8 * sub;
        float h[8];
#pragma unroll
        for (int oi = 0; oi < 8; oi++) {
            int o = ob + oi;
            float s = sb1[o];
#pragma unroll
            for (int kk = 0; kk < D_K; kk++) s = fmaf(att[kk], sW1[o * 9 + kk], s);
            h[oi] = s;
        }
        // layernorm 1 + gelu
        {
            float ls = 0.0f;
#pragma unroll
            for (int oi = 0; oi < 8; oi++) ls += h[oi];
            ls += __shfl_xor_sync(gmask, ls, 1);
            ls += __shfl_xor_sync(gmask, ls, 2);
            float mu = ls * (1.0f / H1);
            float lv = 0.0f;
#pragma unroll
            for (int oi = 0; oi < 8; oi++) { float d = h[oi] - mu; lv = fmaf(d, d, lv); }
            lv += __shfl_xor_sync(gmask, lv, 1);
            lv += __shfl_xor_sync(gmask, lv, 2);
            float inv = rsqrtf(lv * (1.0f / H1) + 1e-5f);
#pragma unroll
            for (int oi = 0; oi < 8; oi++)
                h[oi] = gelu_exact((h[oi] - mu) * inv * sg1[ob + oi] + sB1[ob + oi]);
        }
        // rmsnorm -> shared -> linear -> relu -> residual
        {
            float ss = 0.0f;
#pragma unroll
            for (int oi = 0; oi < 8; oi++) ss = fmaf(h[oi], h[oi], ss);
            ss += __shfl_xor_sync(gmask, ss, 1);
            ss += __shfl_xor_sync(gmask, ss, 2);
            float rms = sqrtf(ss * (1.0f / H1));
            float rinv = 1.0f / (rms + 1e-6f);
#pragma unroll
            for (int oi = 0; oi < 8; oi++)
                sh[rl * 33 + ob + oi] = h[oi] * rinv * srw[ob + oi];
            __syncwarp();
#pragma unroll
            for (int oi = 0; oi < 8; oi++) {
                int o = ob + oi;
                float s = sbr[o];
#pragma unroll
                for (int kk = 0; kk < H1; kk++)
                    s = fmaf(sh[rl * 33 + kk], sWr[o * 33 + kk], s);
                h[oi] += fmaxf(s, 0.0f);
            }
        }
        // layernorm 2
        {
            float ls = 0.0f;
#pragma unroll
            for (int oi = 0; oi < 8; oi++) ls += h[oi];
            ls += __shfl_xor_sync(gmask, ls, 1);
            ls += __shfl_xor_sync(gmask, ls, 2);
            float mu = ls * (1.0f / H1);
            float lv = 0.0f;
#pragma unroll
            for (int oi = 0; oi < 8; oi++) { float d = h[oi] - mu; lv = fmaf(d, d, lv); }
            lv += __shfl_xor_sync(gmask, lv, 1);
            lv += __shfl_xor_sync(gmask, lv, 2);
            float inv = rsqrtf(lv * (1.0f / H1) + 1e-5f);
#pragma unroll
            for (int oi = 0; oi < 8; oi++)
                h[oi] = (h[oi] - mu) * inv * sg2[ob + oi] + sB2[ob + oi];
        }
        // publish h, then linear 32->16 + gelu + linear 16->1 (4 outputs/lane)
        __syncwarp();
#pragma unroll
        for (int oi = 0; oi < 8; oi++) sh[rl * 33 + ob + oi] = h[oi];
        __syncwarp();
        float part = 0.0f;
#pragma unroll
        for (int oi = 0; oi < 4; oi++) {
            int o = 4 * sub + oi;
            float s = sb2[o];
#pragma unroll
            for (int kk = 0; kk < H1; kk++)
                s = fmaf(sh[rl * 33 + kk], sW2[o * 33 + kk], s);
            part = fmaf(gelu_exact(s), sW3[o], part);
        }
        part += __shfl_xor_sync(gmask, part, 1);
        part += __shfl_xor_sync(gmask, part, 2);
        if (sub == 0) g_logits[i] = part + sb3;
    }

    grid_barrier(&g_bar2);

    // ================= Phase 3: per-edge-segment softmax (64 edges/block) ====
    if (tid < 64) {
        int e = blockIdx.x * 64 + tid;
        int c = min(g_ecnt[e], ECAP);
        g_ecnt[e] = 0;                         // reset for next replay
        if (c > 0) {
            float mx = -1e30f;
            for (int jj = 0; jj < c; jj++)
                mx = fmaxf(mx, g_logits[g_emem[e * ECAP + jj]]);
            float sum = 0.0f;
            for (int jj = 0; jj < c; jj++)
                sum += expf(g_logits[g_emem[e * ECAP + jj]] - mx);
            float inv = 1.0f / sum;
            for (int jj = 0; jj < c; jj++) {
                int j = g_emem[e * ECAP + jj];
                out[j] = expf(g_logits[j] - mx) * inv;
            }
        }
    }
    {
        int gtid = blockIdx.x * TPB + tid;
        if (gtid < N_TRI) g_cnt[gtid] = 0;     // reset for next replay
    }

    // ---- final arrival: last block resets barrier counters ----
    __syncthreads();
    if (tid == 0) {
        __threadfence();
        unsigned prev = atomicAdd(&g_bar3, 1u);
        if (prev == NB - 1u) {
            g_bar1 = 0u; g_bar2 = 0u; g_bar3 = 0u;
            __threadfence();
        }
    }
}

extern "C" void kernel_launch(void* const* d_in, const int* in_sizes, int n_in,
                              void* d_out, int out_size) {
    const float* ef   = (const float*)d_in[0];
    const int*   eids = (const int*)  d_in[1];
    const int*   tri  = (const int*)  d_in[2];
    const float* Wq = (const float*)d_in[3];  const float* bq = (const float*)d_in[4];
    const float* Wk = (const float*)d_in[5];  const float* bk = (const float*)d_in[6];
    const float* Wv = (const float*)d_in[7];  const float* bv = (const float*)d_in[8];
    const float* W1 = (const float*)d_in[9];  const float* b1 = (const float*)d_in[10];
    const float* g1 = (const float*)d_in[11]; const float* B1 = (const float*)d_in[12];
    const float* rw = (const float*)d_in[13];
    const float* Wr = (const float*)d_in[14]; const float* br = (const float*)d_in[15];
    const float* g2 = (const float*)d_in[16]; const float* B2 = (const float*)d_in[17];
    const float* W2 = (const float*)d_in[18]; const float* b2 = (const float*)d_in[19];
    const float* W3 = (const float*)d_in[20]; const float* b3 = (const float*)d_in[21];
    float* out = (float*)d_out;

    k_fused<<<NB, TPB>>>(ef, eids, tri, Wq, bq, Wk, bk, Wv, bv,
                         W1, b1, g1, B1, rw, Wr, br, g2, B2, W2, b2, W3, b3, out);
}